// round 5
// baseline (speedup 1.0000x reference)
#include <cuda_runtime.h>

// CRF NLL: B=1024, T=512, C=53, BOS=1, EOS=2
// One WARP per 2 batches (ILP2): two independent scaled-prob recurrences
// interleaved in one warp; shared exp(transition) registers; no cross-warp sync.
// Packed f32x2 FMA, 4-step chunked emission prefetch, renorm every 4 steps,
// fused last-block reduction.

#define Bn   1024
#define Tn   512
#define Cn   53
#define BOSi 1
#define EOSi 2

__device__ float    g_partial[Bn];
__device__ unsigned g_ticket;   // zero-init; reset by last block each launch

typedef unsigned long long ull;

__device__ __forceinline__ ull pack2(float a, float b) {
    ull r; asm("mov.b64 %0, {%1,%2};" : "=l"(r) : "f"(a), "f"(b)); return r;
}
__device__ __forceinline__ void unpack2(ull v, float& a, float& b) {
    asm("mov.b64 {%0,%1}, %2;" : "=f"(a), "=f"(b) : "l"(v));
}
__device__ __forceinline__ void fma2(ull& acc, ull a, ull b) {
    asm("fma.rn.f32x2 %0, %1, %2, %0;" : "+l"(acc) : "l"(a), "l"(b));
}
__device__ __forceinline__ ull add2(ull a, ull b) {
    ull r; asm("add.rn.f32x2 %0, %1, %2;" : "=l"(r) : "l"(a), "l"(b)); return r;
}
__device__ __forceinline__ void lds_v2u64(unsigned addr, ull& x, ull& y) {
    asm volatile("ld.shared.v2.u64 {%0,%1}, [%2];" : "=l"(x), "=l"(y) : "r"(addr));
}

// dot over p (smem addr PA, 56 floats) against this lane's e-columns -> S0,S1
#define DOT(PA, S0, S1) do {                                                \
    ull a0_=0, a1_=0, a2_=0, a3_=0;                                         \
    _Pragma("unroll")                                                       \
    for (int k_ = 0; k_ < 14; k_++) {                                       \
        ull x_, y_;                                                         \
        lds_v2u64((PA) + 16u * k_, x_, y_);                                 \
        fma2(a0_, x_, eA[2*k_]);  fma2(a1_, y_, eA[2*k_+1]);                \
        fma2(a2_, x_, eB[2*k_]);  fma2(a3_, y_, eB[2*k_+1]);                \
    }                                                                       \
    float u_, v_;                                                           \
    unpack2(add2(a0_, a1_), u_, v_); S0 = u_ + v_;                          \
    unpack2(add2(a2_, a3_), u_, v_); S1 = u_ + v_;                          \
} while (0)

// epilogue: optional renorm by old p[0], scale by exp(emissions), store, flip
#define FIN(S0, S1, E0, E1, Lv, PROW, BUFV, P0, P1, REN) do {               \
    float r_ = 1.0f;                                                        \
    if (REN) {                                                              \
        float s_ = (PROW)[(BUFV) * 64];                                     \
        r_ = __fdividef(1.0f, s_);                                          \
        Lv += __logf(s_);                                                   \
    }                                                                       \
    float n0_ = (S0) * r_ * __expf(E0);                                     \
    float n1_ = (S1) * r_ * __expf(E1);                                     \
    (BUFV) ^= 1;                                                            \
    *(float2*)((PROW) + (BUFV) * 64 + 2 * lane) = make_float2(n0_, n1_);    \
    P0 = n0_; P1 = n1_;                                                     \
} while (0)

// burst-load 4 steps of emissions for both columns of one batch
#define LOAD4(P0A, P1A, EMB, BASEROW) do {                                  \
    _Pragma("unroll")                                                       \
    for (int j_ = 0; j_ < 4; j_++) {                                        \
        int rr_ = (BASEROW) + j_; if (rr_ > Tn - 1) rr_ = Tn - 1;           \
        const float* rp_ = (EMB) + (size_t)rr_ * Cn;                        \
        P0A[j_] = __ldg(rp_ + c0v);                                         \
        P1A[j_] = __ldg(rp_ + c1v);                                         \
    }                                                                       \
} while (0)

__global__ void __launch_bounds__(64)
crf_fwd_kernel(const float* __restrict__ em,
               const int*   __restrict__ tags,
               const float* __restrict__ mask,
               const float* __restrict__ trans,
               float* __restrict__ out)
{
    __shared__ float trs[Cn * Cn];
    __shared__ __align__(16) float p_sm[2][2][2][64];  // [warp][batch][buf][slot]
    __shared__ float rsum[2];
    __shared__ int   slast;

    const int tid  = threadIdx.x;
    const int lane = tid & 31;
    const int w    = tid >> 5;
    const int bA   = blockIdx.x * 4 + w * 2;
    const int bB   = bA + 1;

    for (int i = tid; i < Cn * Cn; i += 64) trs[i] = trans[i];
    __syncthreads();

    const int  c0  = 2 * lane,            c1  = 2 * lane + 1;
    const bool okA = (c0 < Cn);           const bool okB = (c1 < Cn);
    const int  c0v = okA ? c0 : (Cn - 1); const int  c1v = okB ? c1 : (Cn - 1);

    const float* embA = em + (size_t)bA * Tn * Cn;
    const float* embB = em + (size_t)bB * Tn * Cn;
    const int*   tgA  = tags + bA * Tn;
    const int*   tgB  = tags + bB * Tn;

    float* prowA = &p_sm[w][0][0][0];
    float* prowB = &p_sm[w][1][0][0];
    const unsigned pbA = (unsigned)__cvta_generic_to_shared(prowA);
    const unsigned pbB = (unsigned)__cvta_generic_to_shared(prowB);

    // ---- sequence lengths ----
    float msA = 0.f, msB = 0.f;
    for (int i = lane; i < Tn; i += 32) {
        msA += mask[bA * Tn + i];
        msB += mask[bB * Tn + i];
    }
#pragma unroll
    for (int off = 16; off; off >>= 1) {
        msA += __shfl_xor_sync(~0u, msA, off);
        msB += __shfl_xor_sync(~0u, msB, off);
    }
    const int tlA = (int)msA, tlB = (int)msB;
    const int tmin = tlA < tlB ? tlA : tlB;
    const int tmax = tlA > tlB ? tlA : tlB;

    // ---- packed exp(transition) columns (shared by both batches) ----
    ull eA[28], eB[28];
#pragma unroll
    for (int k = 0; k < 28; k++) {
        int r0 = 2 * k, r1 = 2 * k + 1;
        float a0 = (okA && r0 < Cn) ? __expf(trs[r0 * Cn + c0]) : 0.f;
        float a1 = (okA && r1 < Cn) ? __expf(trs[r1 * Cn + c0]) : 0.f;
        float b0 = (okB && r0 < Cn) ? __expf(trs[r0 * Cn + c1]) : 0.f;
        float b1 = (okB && r1 < Cn) ? __expf(trs[r1 * Cn + c1]) : 0.f;
        eA[k] = pack2(a0, a1);
        eB[k] = pack2(b0, b1);
    }

    // ---- init both chains ----
    float pA0 = okA ? __expf(trs[BOSi * Cn + c0] + embA[Cn + c0]) : 0.f;
    float pA1 = okB ? __expf(trs[BOSi * Cn + c1] + embA[Cn + c1]) : 0.f;
    float pB0 = okA ? __expf(trs[BOSi * Cn + c0] + embB[Cn + c0]) : 0.f;
    float pB1 = okB ? __expf(trs[BOSi * Cn + c1] + embB[Cn + c1]) : 0.f;
    int bufA = 0, bufB = 0;
    *(float2*)(prowA + 2 * lane) = make_float2(pA0, pA1);
    *(float2*)(prowB + 2 * lane) = make_float2(pB0, pB1);
    __syncwarp();

    float LA = 0.f, LB = 0.f;
    float xA0[4], xA1[4], xB0[4], xB1[4];   // chunk cur
    float yA0[4], yA1[4], yB0[4], yB1[4];   // chunk next

    // ================= dual phase: both chains, up to tmin =================
    LOAD4(xA0, xA1, embA, 2);
    LOAD4(xB0, xB1, embB, 2);
    int base = 2;
    for (;;) {
        if (base + 4 > tmin) break;
        LOAD4(yA0, yA1, embA, base + 4);
        LOAD4(yB0, yB1, embB, base + 4);
#pragma unroll
        for (int j = 0; j < 4; j++) {
            const bool ren = (((base + j) & 3) == 2);
            float sa0, sa1, sb0, sb1;
            DOT(pbA + (unsigned)bufA * 256u, sa0, sa1);
            DOT(pbB + (unsigned)bufB * 256u, sb0, sb1);
            FIN(sa0, sa1, xA0[j], xA1[j], LA, prowA, bufA, pA0, pA1, ren);
            FIN(sb0, sb1, xB0[j], xB1[j], LB, prowB, bufB, pB0, pB1, ren);
            __syncwarp();
        }
        base += 4;
        if (base + 4 > tmin) break;
        LOAD4(xA0, xA1, embA, base + 4);
        LOAD4(xB0, xB1, embB, base + 4);
#pragma unroll
        for (int j = 0; j < 4; j++) {
            const bool ren = (((base + j) & 3) == 2);
            float sa0, sa1, sb0, sb1;
            DOT(pbA + (unsigned)bufA * 256u, sa0, sa1);
            DOT(pbB + (unsigned)bufB * 256u, sb0, sb1);
            FIN(sa0, sa1, yA0[j], yA1[j], LA, prowA, bufA, pA0, pA1, ren);
            FIN(sb0, sb1, yB0[j], yB1[j], LB, prowB, bufB, pB0, pB1, ren);
            __syncwarp();
        }
        base += 4;
    }
    for (int t = base; t < tmin; t++) {   // dual scalar tail (< 4 steps)
        const bool ren = ((t & 3) == 2);
        float ea0 = __ldg(embA + (size_t)t * Cn + c0v);
        float ea1 = __ldg(embA + (size_t)t * Cn + c1v);
        float eb0 = __ldg(embB + (size_t)t * Cn + c0v);
        float eb1 = __ldg(embB + (size_t)t * Cn + c1v);
        float sa0, sa1, sb0, sb1;
        DOT(pbA + (unsigned)bufA * 256u, sa0, sa1);
        DOT(pbB + (unsigned)bufB * 256u, sb0, sb1);
        FIN(sa0, sa1, ea0, ea1, LA, prowA, bufA, pA0, pA1, ren);
        FIN(sb0, sb1, eb0, eb1, LB, prowB, bufB, pB0, pB1, ren);
        __syncwarp();
    }

    // ================= single phase: longer chain, tmin..tmax ==============
    if (tmax > tmin) {
        const bool contA = (tlA > tlB);
        const float* embS = contA ? embA : embB;
        float* prowS = contA ? prowA : prowB;
        unsigned pbS = contA ? pbA : pbB;
        int   bufS = contA ? bufA : bufB;
        float LS   = contA ? LA : LB;
        float pS0  = contA ? pA0 : pB0;
        float pS1  = contA ? pA1 : pB1;

        LOAD4(xA0, xA1, embS, tmin);
        int bs = tmin;
        for (;;) {
            if (bs + 4 > tmax) break;
            LOAD4(yA0, yA1, embS, bs + 4);
#pragma unroll
            for (int j = 0; j < 4; j++) {
                const bool ren = (((bs + j) & 3) == 2);
                float s0, s1;
                DOT(pbS + (unsigned)bufS * 256u, s0, s1);
                FIN(s0, s1, xA0[j], xA1[j], LS, prowS, bufS, pS0, pS1, ren);
                __syncwarp();
            }
            bs += 4;
            if (bs + 4 > tmax) break;
            LOAD4(xA0, xA1, embS, bs + 4);
#pragma unroll
            for (int j = 0; j < 4; j++) {
                const bool ren = (((bs + j) & 3) == 2);
                float s0, s1;
                DOT(pbS + (unsigned)bufS * 256u, s0, s1);
                FIN(s0, s1, yA0[j], yA1[j], LS, prowS, bufS, pS0, pS1, ren);
                __syncwarp();
            }
            bs += 4;
        }
        for (int t = bs; t < tmax; t++) {
            const bool ren = ((t & 3) == 2);
            float e0 = __ldg(embS + (size_t)t * Cn + c0v);
            float e1 = __ldg(embS + (size_t)t * Cn + c1v);
            float s0, s1;
            DOT(pbS + (unsigned)bufS * 256u, s0, s1);
            FIN(s0, s1, e0, e1, LS, prowS, bufS, pS0, pS1, ren);
            __syncwarp();
        }
        if (contA) { LA = LS; pA0 = pS0; pA1 = pS1; }
        else       { LB = LS; pB0 = pS0; pB1 = pS1; }
    }

    // ---- partitions ----
    float eosf0 = __expf(trs[c0v * Cn + EOSi]);
    float eosf1 = __expf(trs[c1v * Cn + EOSi]);
    float fA = pA0 * eosf0 + pA1 * eosf1;   // invalid cols have p==0
    float fB = pB0 * eosf0 + pB1 * eosf1;
#pragma unroll
    for (int off = 16; off; off >>= 1) {
        fA += __shfl_xor_sync(~0u, fA, off);
        fB += __shfl_xor_sync(~0u, fB, off);
    }
    float partA = LA + __logf(fA);
    float partB = LB + __logf(fB);

    // ---- gold-path scores ----
    float sA = 0.f, sB = 0.f;
    for (int t = 2 + lane; t < tlA; t += 32) {
        int a = tgA[t - 1], c = tgA[t];
        sA += embA[(size_t)t * Cn + c] + trs[a * Cn + c];
    }
    for (int t = 2 + lane; t < tlB; t += 32) {
        int a = tgB[t - 1], c = tgB[t];
        sB += embB[(size_t)t * Cn + c] + trs[a * Cn + c];
    }
#pragma unroll
    for (int off = 16; off; off >>= 1) {
        sA += __shfl_xor_sync(~0u, sA, off);
        sB += __shfl_xor_sync(~0u, sB, off);
    }

    if (lane == 0) {
        int t1A = tgA[1], t1B = tgB[1];
        float firstA = trs[BOSi * Cn + t1A] + embA[Cn + t1A];
        float firstB = trs[BOSi * Cn + t1B] + embB[Cn + t1B];
        int ltA = tgA[tlA], ltB = tgB[tlB];
        g_partial[bA] = partA - (firstA + sA + trs[ltA * Cn + EOSi]);
        g_partial[bB] = partB - (firstB + sB + trs[ltB * Cn + EOSi]);
    }

    // ---- fused reduction: last block sums all partials ----
    __threadfence();
    __syncthreads();
    if (tid == 0) {
        unsigned tk = atomicAdd(&g_ticket, 1u);
        slast = (tk == (unsigned)(gridDim.x - 1)) ? 1 : 0;
    }
    __syncthreads();
    if (slast) {
        __threadfence();
        float acc = 0.f;
        for (int i = tid; i < Bn; i += 64) acc += __ldcg(&g_partial[i]);
#pragma unroll
        for (int off = 16; off; off >>= 1) acc += __shfl_xor_sync(~0u, acc, off);
        if (lane == 0) rsum[w] = acc;
        __syncthreads();
        if (tid == 0) {
            out[0] = rsum[0] + rsum[1];
            g_ticket = 0;   // reset for next graph replay
        }
    }
}

extern "C" void kernel_launch(void* const* d_in, const int* in_sizes, int n_in,
                              void* d_out, int out_size)
{
    const float* em    = (const float*)d_in[0];
    const int*   tags  = (const int*)  d_in[1];
    const float* mask  = (const float*)d_in[2];
    const float* trans = (const float*)d_in[3];
    float* out = (float*)d_out;

    crf_fwd_kernel<<<Bn / 4, 64>>>(em, tags, mask, trans, out);
}

// round 6
// speedup vs baseline: 1.0851x; 1.0851x over previous
#include <cuda_runtime.h>

// CRF NLL: B=1024, T=512, C=53, BOS=1, EOS=2
// One WARP per batch (4 warps / 128-thr block), 2 output columns per lane.
// Scaled-prob forward recurrence: 8-deep split accumulators (chain=28),
// renorm every 4 steps via register shfl (off critical path),
// emission exp precomputed at chunk load, fused last-block reduction.

#define Bn   1024
#define Tn   512
#define Cn   53
#define BOSi 1
#define EOSi 2

__device__ float    g_partial[Bn];
__device__ unsigned g_ticket;   // zero-init; reset by last block each launch

typedef unsigned long long ull;

__device__ __forceinline__ ull pack2(float a, float b) {
    ull r; asm("mov.b64 %0, {%1,%2};" : "=l"(r) : "f"(a), "f"(b)); return r;
}
__device__ __forceinline__ void unpack2(ull v, float& a, float& b) {
    asm("mov.b64 {%0,%1}, %2;" : "=f"(a), "=f"(b) : "l"(v));
}
__device__ __forceinline__ void fma2(ull& acc, ull a, ull b) {
    asm("fma.rn.f32x2 %0, %1, %2, %0;" : "+l"(acc) : "l"(a), "l"(b));
}
__device__ __forceinline__ ull add2(ull a, ull b) {
    ull r; asm("add.rn.f32x2 %0, %1, %2;" : "=l"(r) : "l"(a), "l"(b)); return r;
}
__device__ __forceinline__ void lds_v2u64(unsigned addr, ull& x, ull& y) {
    asm volatile("ld.shared.v2.u64 {%0,%1}, [%2];" : "=l"(x), "=l"(y) : "r"(addr));
}

// one forward step. E0/E1 are PRE-EXPONENTIATED emissions. REN: renorm step.
#define CRF_STEP(E0, E1, REN) do {                                         \
    /* renorm factor from lane0's register p0 (previous step's p[0]) */    \
    float rv_ = 1.0f;                                                      \
    if (REN) {                                                             \
        float s_ = __shfl_sync(~0u, p0, 0);                                \
        rv_ = __fdividef(1.0f, s_);                                        \
        L += __logf(s_);                                                   \
    }                                                                      \
    float re0_ = rv_ * (E0);                                               \
    float re1_ = rv_ * (E1);                                               \
    unsigned pa_ = pbase + (unsigned)buf * 256u;                           \
    ull A0_=0,A1_=0,A2_=0,A3_=0,B0_=0,B1_=0,B2_=0,B3_=0;                   \
    _Pragma("unroll")                                                      \
    for (int i_ = 0; i_ < 14; i_ += 2) {                                   \
        ull x_, y_, x2_, y2_;                                              \
        lds_v2u64(pa_ + 16u * i_,       x_,  y_);                          \
        lds_v2u64(pa_ + 16u * (i_ + 1), x2_, y2_);                         \
        fma2(A0_, x_,  eA[2*i_]);     fma2(A1_, y_,  eA[2*i_+1]);          \
        fma2(B0_, x_,  eB[2*i_]);     fma2(B1_, y_,  eB[2*i_+1]);          \
        fma2(A2_, x2_, eA[2*i_+2]);   fma2(A3_, y2_, eA[2*i_+3]);          \
        fma2(B2_, x2_, eB[2*i_+2]);   fma2(B3_, y2_, eB[2*i_+3]);          \
    }                                                                      \
    float u_, v_, dA_, dB_;                                                \
    unpack2(add2(add2(A0_, A1_), add2(A2_, A3_)), u_, v_); dA_ = u_ + v_;  \
    unpack2(add2(add2(B0_, B1_), add2(B2_, B3_)), u_, v_); dB_ = u_ + v_;  \
    float n0_ = dA_ * re0_;                                                \
    float n1_ = dB_ * re1_;                                                \
    buf ^= 1;                                                              \
    *(float2*)(prow + buf * 64 + 2 * lane) = make_float2(n0_, n1_);        \
    __syncwarp();                                                          \
    p0 = n0_; p1 = n1_;                                                    \
} while (0)

// burst-load 4 steps of emissions, pre-exponentiated
#define LOAD4EXP(P0A, P1A, BASEROW) do {                                   \
    _Pragma("unroll")                                                      \
    for (int j_ = 0; j_ < 4; j_++) {                                       \
        int rr_ = (BASEROW) + j_; if (rr_ > Tn - 1) rr_ = Tn - 1;          \
        const float* rp_ = emb + (size_t)rr_ * Cn;                         \
        P0A[j_] = __expf(__ldg(rp_ + c0v));                                \
        P1A[j_] = __expf(__ldg(rp_ + c1v));                                \
    }                                                                      \
} while (0)

__global__ void __launch_bounds__(128)
crf_fwd_kernel(const float* __restrict__ em,
               const int*   __restrict__ tags,
               const float* __restrict__ mask,
               const float* __restrict__ trans,
               float* __restrict__ out)
{
    __shared__ float trs[Cn * Cn];
    __shared__ __align__(16) float p_sm[4][2][64];  // [warp][buf][slot]
    __shared__ float rsum[4];
    __shared__ int   slast;

    const int tid  = threadIdx.x;
    const int lane = tid & 31;
    const int w    = tid >> 5;
    const int b    = blockIdx.x * 4 + w;

    for (int i = tid; i < Cn * Cn; i += 128) trs[i] = trans[i];
    __syncthreads();

    const int  c0  = 2 * lane,            c1  = 2 * lane + 1;
    const bool okA = (c0 < Cn);           const bool okB = (c1 < Cn);
    const int  c0v = okA ? c0 : (Cn - 1); const int  c1v = okB ? c1 : (Cn - 1);

    const float* emb = em + (size_t)b * Tn * Cn;
    const int*   tg  = tags + b * Tn;
    float* prow = &p_sm[w][0][0];
    const unsigned pbase = (unsigned)__cvta_generic_to_shared(prow);

    // ---- sequence length = sum(mask), per warp ----
    float ms = 0.f;
    for (int i = lane; i < Tn; i += 32) ms += mask[b * Tn + i];
#pragma unroll
    for (int off = 16; off; off >>= 1) ms += __shfl_xor_sync(~0u, ms, off);
    const int tl = (int)ms;   // steps for t in [2, tl)

    // ---- packed exp(transition) columns for this lane's 2 output cols ----
    ull eA[28], eB[28];
#pragma unroll
    for (int k = 0; k < 28; k++) {
        int r0 = 2 * k, r1 = 2 * k + 1;
        float a0 = (okA && r0 < Cn) ? __expf(trs[r0 * Cn + c0]) : 0.f;
        float a1 = (okA && r1 < Cn) ? __expf(trs[r1 * Cn + c0]) : 0.f;
        float b0 = (okB && r0 < Cn) ? __expf(trs[r0 * Cn + c1]) : 0.f;
        float b1 = (okB && r1 < Cn) ? __expf(trs[r1 * Cn + c1]) : 0.f;
        eA[k] = pack2(a0, a1);
        eB[k] = pack2(b0, b1);
    }

    // ---- init: p = exp(T[BOS,c] + em[b,1,c]) (0 for padding cols) ----
    float p0 = okA ? __expf(trs[BOSi * Cn + c0] + emb[Cn + c0]) : 0.f;
    float p1 = okB ? __expf(trs[BOSi * Cn + c1] + emb[Cn + c1]) : 0.f;
    int buf = 0;
    *(float2*)(prow + 2 * lane) = make_float2(p0, p1);
    __syncwarp();

    float L = 0.f;
    float xa[4], xb[4], ya[4], yb[4];  // pre-exponentiated emission chunks

    LOAD4EXP(xa, xb, 2);
    int base = 2;
    for (;;) {
        if (base + 4 > tl) break;
        LOAD4EXP(ya, yb, base + 4);
        CRF_STEP(xa[0], xb[0], true);
        CRF_STEP(xa[1], xb[1], false);
        CRF_STEP(xa[2], xb[2], false);
        CRF_STEP(xa[3], xb[3], false);
        base += 4;
        if (base + 4 > tl) break;
        LOAD4EXP(xa, xb, base + 4);
        CRF_STEP(ya[0], yb[0], true);
        CRF_STEP(ya[1], yb[1], false);
        CRF_STEP(ya[2], yb[2], false);
        CRF_STEP(ya[3], yb[3], false);
        base += 4;
    }
    for (int t = base; t < tl; t++) {   // scalar tail (< 4 steps)
        float e0 = __expf(__ldg(emb + (size_t)t * Cn + c0v));
        float e1 = __expf(__ldg(emb + (size_t)t * Cn + c1v));
        CRF_STEP(e0, e1, false);
    }

    // ---- partition = L + log( sum_c p_c * exp(T[c,EOS]) ) ----
    // (padding cols have p==0, so clamped-index exp factors are harmless)
    float f = p0 * __expf(trs[c0v * Cn + EOSi]) + p1 * __expf(trs[c1v * Cn + EOSi]);
#pragma unroll
    for (int off = 16; off; off >>= 1) f += __shfl_xor_sync(~0u, f, off);
    float partition = L + __logf(f);

    // ---- gold-path score ----
    float s = 0.f;
    for (int t = 2 + lane; t < tl; t += 32) {
        int a = tg[t - 1], c = tg[t];
        s += emb[(size_t)t * Cn + c] + trs[a * Cn + c];
    }
#pragma unroll
    for (int off = 16; off; off >>= 1) s += __shfl_xor_sync(~0u, s, off);

    if (lane == 0) {
        int   t1    = tg[1];
        float first = trs[BOSi * Cn + t1] + emb[Cn + t1];
        int   lt    = tg[tl];   // tags at index == length
        float score = first + s + trs[lt * Cn + EOSi];
        g_partial[b] = partition - score;
    }

    // ---- fused reduction: last block sums all partials ----
    __threadfence();
    __syncthreads();
    if (tid == 0) {
        unsigned tk = atomicAdd(&g_ticket, 1u);
        slast = (tk == (unsigned)(gridDim.x - 1)) ? 1 : 0;
    }
    __syncthreads();
    if (slast) {
        __threadfence();
        float acc = 0.f;
        for (int i = tid; i < Bn; i += 128) acc += __ldcg(&g_partial[i]);
#pragma unroll
        for (int off = 16; off; off >>= 1) acc += __shfl_xor_sync(~0u, acc, off);
        if (lane == 0) rsum[w] = acc;
        __syncthreads();
        if (tid == 0) {
            out[0] = rsum[0] + rsum[1] + rsum[2] + rsum[3];
            g_ticket = 0;   // reset for next graph replay
        }
    }
}

extern "C" void kernel_launch(void* const* d_in, const int* in_sizes, int n_in,
                              void* d_out, int out_size)
{
    const float* em    = (const float*)d_in[0];
    const int*   tags  = (const int*)  d_in[1];
    const float* mask  = (const float*)d_in[2];
    const float* trans = (const float*)d_in[3];
    float* out = (float*)d_out;

    crf_fwd_kernel<<<Bn / 4, 128>>>(em, tags, mask, trans, out);
}

// round 7
// speedup vs baseline: 1.1325x; 1.0436x over previous
#include <cuda_runtime.h>

// CRF NLL: B=1024, T=512, C=53, BOS=1, EOS=2
// One WARP per batch, 4 warps / 128-thr block (covers all 4 SMSPs).
// Scaled-prob forward recurrence: 8-deep split accumulators, renorm every
// 4 steps via lane-0 shfl, RAW emission prefetch with exp AT USE (hides DRAM),
// fused last-block reduction.

#define Bn   1024
#define Tn   512
#define Cn   53
#define BOSi 1
#define EOSi 2

__device__ float    g_partial[Bn];
__device__ unsigned g_ticket;   // zero-init; reset by last block each launch

typedef unsigned long long ull;

__device__ __forceinline__ ull pack2(float a, float b) {
    ull r; asm("mov.b64 %0, {%1,%2};" : "=l"(r) : "f"(a), "f"(b)); return r;
}
__device__ __forceinline__ void unpack2(ull v, float& a, float& b) {
    asm("mov.b64 {%0,%1}, %2;" : "=f"(a), "=f"(b) : "l"(v));
}
__device__ __forceinline__ void fma2(ull& acc, ull a, ull b) {
    asm("fma.rn.f32x2 %0, %1, %2, %0;" : "+l"(acc) : "l"(a), "l"(b));
}
__device__ __forceinline__ ull add2(ull a, ull b) {
    ull r; asm("add.rn.f32x2 %0, %1, %2;" : "=l"(r) : "l"(a), "l"(b)); return r;
}
__device__ __forceinline__ void lds_v2u64(unsigned addr, ull& x, ull& y) {
    asm volatile("ld.shared.v2.u64 {%0,%1}, [%2];" : "=l"(x), "=l"(y) : "r"(addr));
}

// one forward step. E0/E1 are RAW emissions (exp applied here). REN: renorm.
#define CRF_STEP(E0, E1, REN) do {                                         \
    float rv_ = 1.0f;                                                      \
    if (REN) {                                                             \
        float s_ = __shfl_sync(~0u, p0, 0);                                \
        rv_ = __fdividef(1.0f, s_);                                        \
        L += __logf(s_);                                                   \
    }                                                                      \
    /* exp of prefetched emissions: independent of the dot chain */        \
    float re0_ = rv_ * __expf(E0);                                         \
    float re1_ = rv_ * __expf(E1);                                         \
    unsigned pa_ = pbase + (unsigned)buf * 256u;                           \
    ull A0_=0,A1_=0,A2_=0,A3_=0,B0_=0,B1_=0,B2_=0,B3_=0;                   \
    _Pragma("unroll")                                                      \
    for (int i_ = 0; i_ < 14; i_ += 2) {                                   \
        ull x_, y_, x2_, y2_;                                              \
        lds_v2u64(pa_ + 16u * i_,       x_,  y_);                          \
        lds_v2u64(pa_ + 16u * (i_ + 1), x2_, y2_);                         \
        fma2(A0_, x_,  eA[2*i_]);     fma2(A1_, y_,  eA[2*i_+1]);          \
        fma2(B0_, x_,  eB[2*i_]);     fma2(B1_, y_,  eB[2*i_+1]);          \
        fma2(A2_, x2_, eA[2*i_+2]);   fma2(A3_, y2_, eA[2*i_+3]);          \
        fma2(B2_, x2_, eB[2*i_+2]);   fma2(B3_, y2_, eB[2*i_+3]);          \
    }                                                                      \
    float u_, v_, dA_, dB_;                                                \
    unpack2(add2(add2(A0_, A1_), add2(A2_, A3_)), u_, v_); dA_ = u_ + v_;  \
    unpack2(add2(add2(B0_, B1_), add2(B2_, B3_)), u_, v_); dB_ = u_ + v_;  \
    float n0_ = dA_ * re0_;                                                \
    float n1_ = dB_ * re1_;                                                \
    buf ^= 1;                                                              \
    *(float2*)(prow + buf * 64 + 2 * lane) = make_float2(n0_, n1_);        \
    __syncwarp();                                                          \
    p0 = n0_; p1 = n1_;                                                    \
} while (0)

// burst-load 4 steps of RAW emissions (no exp here — keeps LDG latency hidden)
#define LOAD4(P0A, P1A, BASEROW) do {                                      \
    _Pragma("unroll")                                                      \
    for (int j_ = 0; j_ < 4; j_++) {                                       \
        int rr_ = (BASEROW) + j_; if (rr_ > Tn - 1) rr_ = Tn - 1;          \
        const float* rp_ = emb + (size_t)rr_ * Cn;                         \
        P0A[j_] = __ldg(rp_ + c0v);                                        \
        P1A[j_] = __ldg(rp_ + c1v);                                        \
    }                                                                      \
} while (0)

__global__ void __launch_bounds__(128)
crf_fwd_kernel(const float* __restrict__ em,
               const int*   __restrict__ tags,
               const float* __restrict__ mask,
               const float* __restrict__ trans,
               float* __restrict__ out)
{
    __shared__ float trs[Cn * Cn];
    __shared__ __align__(16) float p_sm[4][2][64];  // [warp][buf][slot]
    __shared__ float rsum[4];
    __shared__ int   slast;

    const int tid  = threadIdx.x;
    const int lane = tid & 31;
    const int w    = tid >> 5;
    const int b    = blockIdx.x * 4 + w;

    for (int i = tid; i < Cn * Cn; i += 128) trs[i] = trans[i];
    __syncthreads();

    const int  c0  = 2 * lane,            c1  = 2 * lane + 1;
    const bool okA = (c0 < Cn);           const bool okB = (c1 < Cn);
    const int  c0v = okA ? c0 : (Cn - 1); const int  c1v = okB ? c1 : (Cn - 1);

    const float* emb = em + (size_t)b * Tn * Cn;
    const int*   tg  = tags + b * Tn;
    float* prow = &p_sm[w][0][0];
    const unsigned pbase = (unsigned)__cvta_generic_to_shared(prow);

    // ---- sequence length = sum(mask), per warp ----
    float ms = 0.f;
    for (int i = lane; i < Tn; i += 32) ms += mask[b * Tn + i];
#pragma unroll
    for (int off = 16; off; off >>= 1) ms += __shfl_xor_sync(~0u, ms, off);
    const int tl = (int)ms;   // steps for t in [2, tl)

    // ---- packed exp(transition) columns for this lane's 2 output cols ----
    ull eA[28], eB[28];
#pragma unroll
    for (int k = 0; k < 28; k++) {
        int r0 = 2 * k, r1 = 2 * k + 1;
        float a0 = (okA && r0 < Cn) ? __expf(trs[r0 * Cn + c0]) : 0.f;
        float a1 = (okA && r1 < Cn) ? __expf(trs[r1 * Cn + c0]) : 0.f;
        float b0 = (okB && r0 < Cn) ? __expf(trs[r0 * Cn + c1]) : 0.f;
        float b1 = (okB && r1 < Cn) ? __expf(trs[r1 * Cn + c1]) : 0.f;
        eA[k] = pack2(a0, a1);
        eB[k] = pack2(b0, b1);
    }

    // ---- init: p = exp(T[BOS,c] + em[b,1,c]) (0 for padding cols) ----
    float p0 = okA ? __expf(trs[BOSi * Cn + c0] + emb[Cn + c0]) : 0.f;
    float p1 = okB ? __expf(trs[BOSi * Cn + c1] + emb[Cn + c1]) : 0.f;
    int buf = 0;
    *(float2*)(prow + 2 * lane) = make_float2(p0, p1);
    __syncwarp();

    float L = 0.f;
    float xa[4], xb[4], ya[4], yb[4];  // RAW emission chunks (double-buffered)

    LOAD4(xa, xb, 2);
    int base = 2;
    for (;;) {
        if (base + 4 > tl) break;
        LOAD4(ya, yb, base + 4);
        CRF_STEP(xa[0], xb[0], true);
        CRF_STEP(xa[1], xb[1], false);
        CRF_STEP(xa[2], xb[2], false);
        CRF_STEP(xa[3], xb[3], false);
        base += 4;
        if (base + 4 > tl) break;
        LOAD4(xa, xb, base + 4);
        CRF_STEP(ya[0], yb[0], true);
        CRF_STEP(ya[1], yb[1], false);
        CRF_STEP(ya[2], yb[2], false);
        CRF_STEP(ya[3], yb[3], false);
        base += 4;
    }
    for (int t = base; t < tl; t++) {   // scalar tail (< 4 steps)
        float e0 = __ldg(emb + (size_t)t * Cn + c0v);
        float e1 = __ldg(emb + (size_t)t * Cn + c1v);
        CRF_STEP(e0, e1, false);
    }

    // ---- partition = L + log( sum_c p_c * exp(T[c,EOS]) ) ----
    float f = p0 * __expf(trs[c0v * Cn + EOSi]) + p1 * __expf(trs[c1v * Cn + EOSi]);
#pragma unroll
    for (int off = 16; off; off >>= 1) f += __shfl_xor_sync(~0u, f, off);
    float partition = L + __logf(f);

    // ---- gold-path score ----
    float s = 0.f;
    for (int t = 2 + lane; t < tl; t += 32) {
        int a = tg[t - 1], c = tg[t];
        s += emb[(size_t)t * Cn + c] + trs[a * Cn + c];
    }
#pragma unroll
    for (int off = 16; off; off >>= 1) s += __shfl_xor_sync(~0u, s, off);

    if (lane == 0) {
        int   t1    = tg[1];
        float first = trs[BOSi * Cn + t1] + emb[Cn + t1];
        int   lt    = tg[tl];   // tags at index == length
        float score = first + s + trs[lt * Cn + EOSi];
        g_partial[b] = partition - score;
    }

    // ---- fused reduction: last block sums all partials ----
    __threadfence();
    __syncthreads();
    if (tid == 0) {
        unsigned tk = atomicAdd(&g_ticket, 1u);
        slast = (tk == (unsigned)(gridDim.x - 1)) ? 1 : 0;
    }
    __syncthreads();
    if (slast) {
        __threadfence();
        float acc = 0.f;
        for (int i = tid; i < Bn; i += 128) acc += __ldcg(&g_partial[i]);
#pragma unroll
        for (int off = 16; off; off >>= 1) acc += __shfl_xor_sync(~0u, acc, off);
        if (lane == 0) rsum[w] = acc;
        __syncthreads();
        if (tid == 0) {
            out[0] = rsum[0] + rsum[1] + rsum[2] + rsum[3];
            g_ticket = 0;   // reset for next graph replay
        }
    }
}

extern "C" void kernel_launch(void* const* d_in, const int* in_sizes, int n_in,
                              void* d_out, int out_size)
{
    const float* em    = (const float*)d_in[0];
    const int*   tags  = (const int*)  d_in[1];
    const float* mask  = (const float*)d_in[2];
    const float* trans = (const float*)d_in[3];
    float* out = (float*)d_out;

    crf_fwd_kernel<<<Bn / 4, 128>>>(em, tags, mask, trans, out);
}